// round 1
// baseline (speedup 1.0000x reference)
#include <cuda_runtime.h>
#include <math.h>

#define NB   512
#define NK   64
#define NC   2048
#define BDIM 256
#define CPT  (NC / BDIM)   // 8 channels per thread

__device__ __forceinline__ float ex2_approx(float x) {
    float r;
    asm("ex2.approx.ftz.f32 %0, %1;" : "=f"(r) : "f"(x));
    return r;
}

__global__ __launch_bounds__(BDIM)
void mixture_kernel(const float* __restrict__ mo,
                    const float* __restrict__ X,
                    float* __restrict__ out) {
    __shared__ float sA[NK], sB[NK], sC[NK], sD[NK], sE[NK], sF[NK], sW[NK];

    const int b   = blockIdx.x;
    const int tid = threadIdx.x;

    // --- per-(b,k) coefficient precompute (first 64 threads) ---
    if (tid < NK) {
        const float* p = mo + ((size_t)b * NK + tid) * 6;
        float w  = p[0];
        float m1 = p[1];
        float m2 = p[2];
        float s1 = p[3];
        float s2 = p[4];
        float r  = p[5];

        float omr2 = 1.0f - r * r;
        float inv  = 1.0f / omr2;
        float is1  = 1.0f / s1;
        float is2  = 1.0f / s2;

        const float L2E = 1.4426950408889634f;   // log2(e)
        // exponent (base-2): a*dx^2 + bb*dx*dy + cc*dy^2
        float a  = -0.5f * inv * is1 * is1 * L2E;
        float bb =  r    * inv * is1 * is2 * L2E;
        float cc = -0.5f * inv * is2 * is2 * L2E;

        // expand around means into raw-x,y quadratic
        sA[tid] = a;
        sB[tid] = bb;
        sC[tid] = cc;
        sD[tid] = -(2.0f * a  * m1 + bb * m2);
        sE[tid] = -(2.0f * cc * m2 + bb * m1);
        sF[tid] = a * m1 * m1 + bb * m1 * m2 + cc * m2 * m2;
        // weight / (2*pi*s1*s2*sqrt(1-r^2))
        sW[tid] = w * is1 * is2 * rsqrtf(omr2) * 0.15915494309189535f;
    }
    __syncthreads();

    // --- per-thread channel state (8 independent chains for ILP) ---
    const float2* Xb = reinterpret_cast<const float2*>(X) + (size_t)b * NC;

    float x[CPT], y[CPT], acc[CPT];
    #pragma unroll
    for (int i = 0; i < CPT; i++) {
        float2 v = Xb[tid + i * BDIM];
        x[i]   = v.x;
        y[i]   = v.y;
        acc[i] = 0.0f;
    }

    // --- mixture accumulation: coefficients hoisted to registers per k ---
    #pragma unroll 4
    for (int k = 0; k < NK; k++) {
        const float A = sA[k];
        const float B = sB[k];
        const float C = sC[k];
        const float D = sD[k];
        const float E = sE[k];
        const float F = sF[k];
        const float W = sW[k];

        #pragma unroll
        for (int i = 0; i < CPT; i++) {
            float u = fmaf(A, x[i], fmaf(B, y[i], D));
            float v = fmaf(C, y[i], E);
            float q = fmaf(u, x[i], fmaf(v, y[i], F));
            acc[i] = fmaf(W, ex2_approx(q), acc[i]);
        }
    }

    float* ob = out + (size_t)b * NC;
    #pragma unroll
    for (int i = 0; i < CPT; i++) {
        ob[tid + i * BDIM] = acc[i];
    }
}

extern "C" void kernel_launch(void* const* d_in, const int* in_sizes, int n_in,
                              void* d_out, int out_size) {
    const float* mo = (const float*)d_in[0];   // model_out: (512, 64, 6) f32
    const float* X  = (const float*)d_in[1];   // X:         (512, 2048, 2) f32
    float* out      = (float*)d_out;           // out:       (512, 2048) f32
    (void)in_sizes; (void)n_in; (void)out_size;

    mixture_kernel<<<NB, BDIM>>>(mo, X, out);
}

// round 2
// speedup vs baseline: 1.1618x; 1.1618x over previous
#include <cuda_runtime.h>
#include <math.h>

#define NB    512
#define NK    64
#define NC    2048
#define BDIM  256
#define SPLIT 2                       // CTAs per batch row
#define CHPB  (NC / SPLIT)            // 1024 channels per CTA
#define CPT   (CHPB / BDIM)           // 4 channels per thread
#define NPAIR (CPT / 2)               // 2 packed pairs per thread

typedef unsigned long long ull;

__device__ __forceinline__ ull pack2(float lo, float hi) {
    ull r;
    asm("mov.b64 %0, {%1, %2};" : "=l"(r) : "f"(lo), "f"(hi));
    return r;
}
__device__ __forceinline__ void unpack2(ull v, float& lo, float& hi) {
    asm("mov.b64 {%0, %1}, %2;" : "=f"(lo), "=f"(hi) : "l"(v));
}
__device__ __forceinline__ ull fma2(ull a, ull b, ull c) {
    ull r;
    asm("fma.rn.f32x2 %0, %1, %2, %3;" : "=l"(r) : "l"(a), "l"(b), "l"(c));
    return r;
}
__device__ __forceinline__ float ex2a(float x) {
    float r;
    asm("ex2.approx.ftz.f32 %0, %1;" : "=f"(r) : "f"(x));
    return r;
}

__global__ __launch_bounds__(BDIM)
void mixture_kernel(const float* __restrict__ mo,
                    const float* __restrict__ X,
                    float* __restrict__ out) {
    // coefficients pre-packed (both f32x2 halves equal) -> ld.shared.b64 broadcast
    __shared__ ull sA[NK], sB[NK], sC[NK], sD[NK], sE[NK], sF[NK], sW[NK];

    const int b    = blockIdx.x / SPLIT;
    const int half = blockIdx.x % SPLIT;
    const int tid  = threadIdx.x;

    // --- per-(b,k) coefficient precompute (first 64 threads) ---
    if (tid < NK) {
        const float* p = mo + ((size_t)b * NK + tid) * 6;
        float w  = p[0];
        float m1 = p[1];
        float m2 = p[2];
        float s1 = p[3];
        float s2 = p[4];
        float r  = p[5];

        float omr2 = 1.0f - r * r;
        float inv  = 1.0f / omr2;
        float is1  = 1.0f / s1;
        float is2  = 1.0f / s2;

        const float L2E = 1.4426950408889634f;   // log2(e)
        float a  = -0.5f * inv * is1 * is1 * L2E;
        float bb =  r    * inv * is1 * is2 * L2E;
        float cc = -0.5f * inv * is2 * is2 * L2E;

        float d = -(2.0f * a  * m1 + bb * m2);
        float e = -(2.0f * cc * m2 + bb * m1);
        float f = a * m1 * m1 + bb * m1 * m2 + cc * m2 * m2;
        float W = w * is1 * is2 * rsqrtf(omr2) * 0.15915494309189535f;

        sA[tid] = pack2(a,  a);
        sB[tid] = pack2(bb, bb);
        sC[tid] = pack2(cc, cc);
        sD[tid] = pack2(d,  d);
        sE[tid] = pack2(e,  e);
        sF[tid] = pack2(f,  f);
        sW[tid] = pack2(W,  W);
    }
    __syncthreads();

    // --- per-thread packed channel state ---
    // pair p covers channels: base + tid + (2p)*BDIM (lo), base + tid + (2p+1)*BDIM (hi)
    const int base = half * CHPB;
    const float2* Xb = reinterpret_cast<const float2*>(X) + (size_t)b * NC + base;

    ull xx[NPAIR], yy[NPAIR], acc[NPAIR];
    #pragma unroll
    for (int p = 0; p < NPAIR; p++) {
        float2 v0 = Xb[tid + (2 * p)     * BDIM];
        float2 v1 = Xb[tid + (2 * p + 1) * BDIM];
        xx[p]  = pack2(v0.x, v1.x);
        yy[p]  = pack2(v0.y, v1.y);
        acc[p] = 0ull;
    }

    // --- mixture accumulation: 3 FFMA2 + 1 MUFU per element ---
    #pragma unroll 4
    for (int k = 0; k < NK; k++) {
        const ull AA = sA[k];
        const ull BB = sB[k];
        const ull CC = sC[k];
        const ull DD = sD[k];
        const ull EE = sE[k];
        const ull FF = sF[k];
        const ull WW = sW[k];

        #pragma unroll
        for (int p = 0; p < NPAIR; p++) {
            ull u = fma2(AA, xx[p], fma2(BB, yy[p], DD));
            ull v = fma2(CC, yy[p], EE);
            ull q = fma2(u, xx[p], fma2(v, yy[p], FF));
            float q0, q1;
            unpack2(q, q0, q1);
            ull ee = pack2(ex2a(q0), ex2a(q1));
            acc[p] = fma2(WW, ee, acc[p]);
        }
    }

    float* ob = out + (size_t)b * NC + base;
    #pragma unroll
    for (int p = 0; p < NPAIR; p++) {
        float a0, a1;
        unpack2(acc[p], a0, a1);
        ob[tid + (2 * p)     * BDIM] = a0;
        ob[tid + (2 * p + 1) * BDIM] = a1;
    }
}

extern "C" void kernel_launch(void* const* d_in, const int* in_sizes, int n_in,
                              void* d_out, int out_size) {
    const float* mo = (const float*)d_in[0];   // model_out: (512, 64, 6) f32
    const float* X  = (const float*)d_in[1];   // X:         (512, 2048, 2) f32
    float* out      = (float*)d_out;           // out:       (512, 2048) f32
    (void)in_sizes; (void)n_in; (void)out_size;

    mixture_kernel<<<NB * SPLIT, BDIM>>>(mo, X, out);
}

// round 3
// speedup vs baseline: 1.2980x; 1.1172x over previous
#include <cuda_runtime.h>
#include <math.h>

#define NB    512
#define NK    64
#define NC    2048
#define BDIM  128
#define SPLIT 2                       // CTAs per batch row
#define CHPB  (NC / SPLIT)            // 1024 channels per CTA
#define CPT   (CHPB / BDIM)           // 8 channels per thread
#define NPAIR (CPT / 2)               // 4 packed pairs per thread

typedef unsigned long long ull;

__device__ __forceinline__ ull pack2(float lo, float hi) {
    ull r;
    asm("mov.b64 %0, {%1, %2};" : "=l"(r) : "f"(lo), "f"(hi));
    return r;
}
__device__ __forceinline__ void unpack2(ull v, float& lo, float& hi) {
    asm("mov.b64 {%0, %1}, %2;" : "=f"(lo), "=f"(hi) : "l"(v));
}
__device__ __forceinline__ ull fma2(ull a, ull b, ull c) {
    ull r;
    asm("fma.rn.f32x2 %0, %1, %2, %3;" : "=l"(r) : "l"(a), "l"(b), "l"(c));
    return r;
}
__device__ __forceinline__ ull add2(ull a, ull b) {
    ull r;
    asm("add.rn.f32x2 %0, %1, %2;" : "=l"(r) : "l"(a), "l"(b));
    return r;
}
__device__ __forceinline__ float ex2a(float x) {
    float r;
    asm("ex2.approx.ftz.f32 %0, %1;" : "=f"(r) : "f"(x));
    return r;
}
__device__ __forceinline__ float lg2a(float x) {
    float r;
    asm("lg2.approx.ftz.f32 %0, %1;" : "=f"(r) : "f"(x));
    return r;
}

__global__ __launch_bounds__(BDIM)
void mixture_kernel(const float* __restrict__ mo,
                    const float* __restrict__ X,
                    float* __restrict__ out) {
    // coefficients pre-packed (both f32x2 halves equal) -> ld.shared.b64 broadcast
    __shared__ ull sA[NK], sB[NK], sC[NK], sD[NK], sE[NK], sF[NK];

    const int b    = blockIdx.x / SPLIT;
    const int half = blockIdx.x % SPLIT;
    const int tid  = threadIdx.x;

    // --- per-(b,k) coefficient precompute (first 64 threads) ---
    if (tid < NK) {
        const float* p = mo + ((size_t)b * NK + tid) * 6;
        float w  = p[0];
        float m1 = p[1];
        float m2 = p[2];
        float s1 = p[3];
        float s2 = p[4];
        float r  = p[5];

        float omr2 = 1.0f - r * r;
        float inv  = 1.0f / omr2;
        float is1  = 1.0f / s1;
        float is2  = 1.0f / s2;

        const float L2E = 1.4426950408889634f;   // log2(e)
        float a  = -0.5f * inv * is1 * is1 * L2E;
        float bb =  r    * inv * is1 * is2 * L2E;
        float cc = -0.5f * inv * is2 * is2 * L2E;

        float d = -(2.0f * a  * m1 + bb * m2);
        float e = -(2.0f * cc * m2 + bb * m1);
        // fold weight/normalizer into the exponent constant:
        //   W * 2^q == 2^(q + log2(W))
        float W = w * is1 * is2 * rsqrtf(omr2) * 0.15915494309189535f;
        float f = a * m1 * m1 + bb * m1 * m2 + cc * m2 * m2 + lg2a(W);

        sA[tid] = pack2(a,  a);
        sB[tid] = pack2(bb, bb);
        sC[tid] = pack2(cc, cc);
        sD[tid] = pack2(d,  d);
        sE[tid] = pack2(e,  e);
        sF[tid] = pack2(f,  f);
    }
    __syncthreads();

    // --- per-thread packed channel state (4 pairs = 8 channels) ---
    const int base = half * CHPB;
    const float2* Xb = reinterpret_cast<const float2*>(X) + (size_t)b * NC + base;

    ull xx[NPAIR], yy[NPAIR], acc[NPAIR];
    #pragma unroll
    for (int p = 0; p < NPAIR; p++) {
        float2 v0 = Xb[tid + (2 * p)     * BDIM];
        float2 v1 = Xb[tid + (2 * p + 1) * BDIM];
        xx[p]  = pack2(v0.x, v1.x);
        yy[p]  = pack2(v0.y, v1.y);
        acc[p] = 0ull;
    }

    // --- mixture accumulation: 3 FFMA2 + 1 MUFU + 0.5 ADD2 per element ---
    #pragma unroll 4
    for (int k = 0; k < NK; k++) {
        const ull AA = sA[k];
        const ull BB = sB[k];
        const ull CC = sC[k];
        const ull DD = sD[k];
        const ull EE = sE[k];
        const ull FF = sF[k];

        #pragma unroll
        for (int p = 0; p < NPAIR; p++) {
            ull u = fma2(AA, xx[p], fma2(BB, yy[p], DD));
            ull v = fma2(CC, yy[p], EE);
            ull q = fma2(u, xx[p], fma2(v, yy[p], FF));
            float q0, q1;
            unpack2(q, q0, q1);
            ull ee = pack2(ex2a(q0), ex2a(q1));
            acc[p] = add2(ee, acc[p]);
        }
    }

    float* ob = out + (size_t)b * NC + base;
    #pragma unroll
    for (int p = 0; p < NPAIR; p++) {
        float a0, a1;
        unpack2(acc[p], a0, a1);
        ob[tid + (2 * p)     * BDIM] = a0;
        ob[tid + (2 * p + 1) * BDIM] = a1;
    }
}

extern "C" void kernel_launch(void* const* d_in, const int* in_sizes, int n_in,
                              void* d_out, int out_size) {
    const float* mo = (const float*)d_in[0];   // model_out: (512, 64, 6) f32
    const float* X  = (const float*)d_in[1];   // X:         (512, 2048, 2) f32
    float* out      = (float*)d_out;           // out:       (512, 2048) f32
    (void)in_sizes; (void)n_in; (void)out_size;

    mixture_kernel<<<NB * SPLIT, BDIM>>>(mo, X, out);
}